// round 15
// baseline (speedup 1.0000x reference)
#include <cuda_runtime.h>
#include <cuda_fp16.h>
#include <math.h>
#include <stdint.h>

// Problem constants (fixed by the reference)
#define Nn   50000
#define Ee   800000
#define IOd  128
#define HIDd 256
#define KQd  256

// ---------------- device scratch (no allocations allowed) ----------------
__device__ __half g_qh[Nn * KQd];
__device__ __half g_kh[Nn * KQd];
__device__ __half g_vh[Nn * HIDd];
__device__ __half g_rh[Nn * HIDd];
__device__ __half g_hh[Nn * HIDd];
__device__ __half g_x0h[Nn * IOd];
__device__ __half g_x1h[Nn * HIDd];
__device__ __half g_wth[327680];    // transposed fp16 weights
__device__ int   g_src[Ee];
__device__ int   g_dst[Ee];
__device__ int   g_csr_src[Ee];
__device__ int   g_deg[Nn];
__device__ int   g_inc[Nn];         // block-local inclusive scan of deg
__device__ int   g_fill[Nn];
#define NB_SCAN 49
__device__ int   g_bsum[NB_SCAN];
__device__ int   g_boff[NB_SCAN];   // exclusive block offsets
__device__ float g_sumf[HIDd];      // zero at call entry; finalize re-zeros
__device__ float g_sumsqf[HIDd];
__device__ float g_mean[HIDd];
__device__ float g_inv[HIDd];
__device__ int   g_flag64[1];

#define WT_L1 0         // [1024 x 128]: Q1,K1,V1,R1
#define WT_L2 131072    // [768 x 256]:  Q2,K2,V2,R2

// ---------------- helpers ----------------
__device__ __forceinline__ uint32_t smem_u32(const void* p) {
    uint32_t a;
    asm("{ .reg .u64 t; cvta.to.shared.u64 t, %1; cvt.u32.u64 %0, t; }" : "=r"(a) : "l"(p));
    return a;
}
__device__ __forceinline__ void cp_async16(uint32_t sm, const void* g) {
    asm volatile("cp.async.cg.shared.global [%0], [%1], 16;" :: "r"(sm), "l"(g));
}
__device__ __forceinline__ void cp_commit() { asm volatile("cp.async.commit_group;"); }
__device__ __forceinline__ void cp_wait1() { asm volatile("cp.async.wait_group 1;"); }
__device__ __forceinline__ void cp_wait0() { asm volatile("cp.async.wait_group 0;"); }
__device__ __forceinline__ void ldsm_x4(uint32_t& r0, uint32_t& r1, uint32_t& r2, uint32_t& r3,
                                        uint32_t addr) {
    asm volatile("ldmatrix.sync.aligned.m8n8.x4.shared.b16 {%0,%1,%2,%3}, [%4];"
                 : "=r"(r0), "=r"(r1), "=r"(r2), "=r"(r3) : "r"(addr));
}

// ---------------- prep: weight transpose->fp16 + x0->fp16 ----------------
struct W8 { const float* w[8]; };
#define PREP_W 327680
#define PREP_TOTAL (PREP_W + Nn * IOd)
__global__ void prep_kernel(W8 ws, const float* __restrict__ x0,
                            __half* __restrict__ Wt, __half* __restrict__ x0h) {
    int i = blockIdx.x * 256 + threadIdx.x;
    if (i >= PREP_TOTAL) return;
    if (i < PREP_W) {
        int seg, base, K, N, dst;
        if (i < 131072)      { seg = i >> 15;       base = seg << 15;          K = 128; N = 256; dst = seg * 32768; }
        else if (i < 262144) { seg = 4 + ((i - 131072) >> 16); base = 131072 + ((seg - 4) << 16); K = 256; N = 256; dst = 131072 + (seg - 4) * 65536; }
        else                 { seg = 6 + ((i - 262144) >> 15); base = 262144 + ((seg - 6) << 15); K = 256; N = 128; dst = 262144 + (seg - 6) * 32768; }
        int il = i - base;
        int k = il / N, n = il % N;
        Wt[dst + n * K + k] = __float2half(ws.w[seg][il]);
    } else {
        int j = i - PREP_W;
        x0h[j] = __float2half(x0[j]);
    }
}

// ---------------- fused HMMA fp16 GEMM: CTA 128x256, 512 thr, warp 64x32 ----
#define SROWH 72

template <int LAYER>
__global__ __launch_bounds__(512) void fused_gemm_kernel(
    const __half* __restrict__ A, const __half* __restrict__ BtAll,
    __half* __restrict__ Oq, __half* __restrict__ Ok,
    __half* __restrict__ Ov, __half* __restrict__ Orr, int M)
{
    constexpr int K = (LAYER == 1) ? 128 : 256;
    extern __shared__ __half smem[];
    __half* As = smem;                      // 2 x 128 x SROWH halves
    __half* Bs = smem + 2 * 128 * SROWH;    // 2 x 256 x SROWH halves

    const int tid = threadIdx.x;
    const int wid = tid >> 5;
    const int lane = tid & 31;
    const int gID = lane >> 2;
    const int tig = lane & 3;
    const int wm = (wid & 1) * 64;          // 2 M-groups
    const int wn = (wid >> 1) * 32;         // 8 N-groups -> 256 cols
    const int m0 = blockIdx.x * 128;
    const int y = blockIdx.y;
    const int nb0 = y * 256;                // row offset into BtAll

    // ldmatrix per-lane offsets
    const int a_row_off = (lane & 15);
    const int a_col_off = (lane >> 4) << 3;
    const int b_row_off = (lane & 7) + ((lane >> 4) << 3);
    const int b_col_off = (lane & 8);

    float c[4][4][4] = {};
    constexpr int NC = K / 64;

    auto stage = [&](int cc, int buf) {
        const int k0 = cc * 64;
        __half* ab = As + buf * (128 * SROWH);
        __half* bb = Bs + buf * (256 * SROWH);
        #pragma unroll
        for (int i = 0; i < 2; i++) {           // A: 128 rows x 64 halves (1024 groups)
            int idx = tid + i * 512;
            int row = idx >> 3, g = idx & 7;
            int gr = m0 + row; if (gr >= M) gr = M - 1;
            cp_async16(smem_u32(ab + row * SROWH + g * 8), A + (size_t)gr * K + k0 + g * 8);
        }
        #pragma unroll
        for (int i = 0; i < 4; i++) {           // B: 256 rows x 64 halves (2048 groups)
            int idx = tid + i * 512;
            int row = idx >> 3, g = idx & 7;
            cp_async16(smem_u32(bb + row * SROWH + g * 8), BtAll + (size_t)(nb0 + row) * K + k0 + g * 8);
        }
        cp_commit();
    };

    stage(0, 0);
    for (int cc = 0; cc < NC; cc++) {
        const int buf = cc & 1;
        if (cc + 1 < NC) { stage(cc + 1, buf ^ 1); cp_wait1(); }
        else             { cp_wait0(); }
        __syncthreads();

        const __half* ab = As + buf * (128 * SROWH);
        const __half* bb = Bs + buf * (256 * SROWH);

        #pragma unroll
        for (int ks = 0; ks < 4; ks++) {
            const int kk = ks * 16;
            uint32_t af[4][4];
            #pragma unroll
            for (int mf = 0; mf < 4; mf++) {
                uint32_t addr = smem_u32(ab + (wm + mf * 16 + a_row_off) * SROWH + kk + a_col_off);
                ldsm_x4(af[mf][0], af[mf][1], af[mf][2], af[mf][3], addr);
            }
            uint32_t bf[4][2];
            #pragma unroll
            for (int np = 0; np < 2; np++) {
                uint32_t addr = smem_u32(bb + (wn + np * 16 + b_row_off) * SROWH + kk + b_col_off);
                ldsm_x4(bf[2 * np][0], bf[2 * np][1], bf[2 * np + 1][0], bf[2 * np + 1][1], addr);
            }
            #pragma unroll
            for (int mf = 0; mf < 4; mf++)
                #pragma unroll
                for (int nf = 0; nf < 4; nf++)
                    asm volatile(
                        "mma.sync.aligned.m16n8k16.row.col.f32.f16.f16.f32 "
                        "{%0,%1,%2,%3}, {%4,%5,%6,%7}, {%8,%9}, {%0,%1,%2,%3};"
                        : "+f"(c[mf][nf][0]), "+f"(c[mf][nf][1]),
                          "+f"(c[mf][nf][2]), "+f"(c[mf][nf][3])
                        : "r"(af[mf][0]), "r"(af[mf][1]), "r"(af[mf][2]), "r"(af[mf][3]),
                          "r"(bf[nf][0]), "r"(bf[nf][1]));
        }
        __syncthreads();
    }

    // output routing (all fp16):
    // layer1: y = 0..3 -> Q,K,V,R full 256-col matrices
    // layer2: y = 0 Q, y = 1 K (256 cols); y = 2: cols<128 -> V else R (128 cols)
    #pragma unroll
    for (int mf = 0; mf < 4; mf++) {
        int row = m0 + wm + mf * 16 + gID;
        #pragma unroll
        for (int nf = 0; nf < 4; nf++) {
            int col_local = wn + nf * 8 + tig * 2;
            __half* hout; int Nout, col;
            if (LAYER == 1) {
                hout = (y == 0) ? Oq : (y == 1) ? Ok : (y == 2) ? Ov : Orr;
                Nout = 256; col = col_local;
            } else {
                if (y == 0)      { hout = Oq; Nout = 256; col = col_local; }
                else if (y == 1) { hout = Ok; Nout = 256; col = col_local; }
                else {
                    if (col_local < 128) { hout = Ov;  Nout = 128; col = col_local; }
                    else                 { hout = Orr; Nout = 128; col = col_local - 128; }
                }
            }
            if (row < M)
                *(__half2*)(hout + (size_t)row * Nout + col) = __floats2half2_rn(c[mf][nf][0], c[mf][nf][1]);
            if (row + 8 < M)
                *(__half2*)(hout + (size_t)(row + 8) * Nout + col) = __floats2half2_rn(c[mf][nf][2], c[mf][nf][3]);
        }
    }
}

// ---------------- setup: zero + edge dtype detect ----------------
__global__ void detect_zero_kernel(const int* __restrict__ ew) {
    int i = blockIdx.x * blockDim.x + threadIdx.x;
    if (i < Nn) { g_deg[i] = 0; g_fill[i] = 0; }
    if (blockIdx.x == 0) {
        __shared__ int nz;
        if (threadIdx.x == 0) nz = 0;
        __syncthreads();
        int stride = Ee / 256;
        int idx = 2 * (threadIdx.x * stride) + 1;
        if (ew[idx] != 0) atomicOr(&nz, 1);
        __syncthreads();
        if (threadIdx.x == 0) g_flag64[0] = nz ? 0 : 1;
    }
}

__global__ void convert_count_kernel(const void* __restrict__ edges) {
    int e = blockIdx.x * blockDim.x + threadIdx.x;
    if (e >= Ee) return;
    int s, d;
    if (g_flag64[0]) {
        const long long* p = (const long long*)edges;
        s = (int)p[e]; d = (int)p[Ee + e];
    } else {
        const int* p = (const int*)edges;
        s = p[e]; d = p[Ee + e];
    }
    g_src[e] = s; g_dst[e] = d;
    atomicAdd(&g_deg[d], 1);
}

// ---------------- CSR scan + scatter ----------------
__global__ void scan1_kernel() {
    __shared__ int sm[1024];
    int i = blockIdx.x * 1024 + threadIdx.x;
    int v = (i < Nn) ? g_deg[i] : 0;
    sm[threadIdx.x] = v;
    __syncthreads();
    for (int off = 1; off < 1024; off <<= 1) {
        int t = (threadIdx.x >= off) ? sm[threadIdx.x - off] : 0;
        __syncthreads();
        sm[threadIdx.x] += t;
        __syncthreads();
    }
    if (i < Nn) g_inc[i] = sm[threadIdx.x];
    if (threadIdx.x == 1023) g_bsum[blockIdx.x] = sm[1023];
}
__global__ void scan2_kernel() {
    __shared__ int sm[64];
    int t = threadIdx.x;
    sm[t] = (t < NB_SCAN) ? g_bsum[t] : 0;
    __syncthreads();
    #pragma unroll
    for (int off = 1; off < 64; off <<= 1) {
        int v = (t >= off) ? sm[t - off] : 0;
        __syncthreads();
        sm[t] += v;
        __syncthreads();
    }
    if (t < NB_SCAN) g_boff[t] = sm[t] - g_bsum[t];
}
__global__ void csr_scatter_kernel() {
    int e = blockIdx.x * blockDim.x + threadIdx.x;
    if (e >= Ee) return;
    int d = g_dst[e];
    int start = g_inc[d] + g_boff[d >> 10] - g_deg[d];
    int pos = start + atomicAdd(&g_fill[d], 1);
    g_csr_src[pos] = g_src[e];
}

// ---------------- attention: online softmax, unroll 8, fused BN stats ------
__device__ __forceinline__ float dot8h(uint4 a, uint4 b) {
    const __half2* ah = (const __half2*)&a;
    const __half2* bh = (const __half2*)&b;
    float p = 0.f;
    #pragma unroll
    for (int i = 0; i < 4; i++) {
        float2 fa = __half22float2(ah[i]);
        float2 fb = __half22float2(bh[i]);
        p += fa.x * fb.x + fa.y * fb.y;
    }
    return p;
}
__device__ __forceinline__ void unpack8h(uint4 a, float* f) {
    const __half2* ah = (const __half2*)&a;
    #pragma unroll
    for (int i = 0; i < 4; i++) {
        float2 t = __half22float2(ah[i]);
        f[2 * i] = t.x; f[2 * i + 1] = t.y;
    }
}
__device__ __forceinline__ void unpack4h(uint2 a, float* f) {
    const __half2* ah = (const __half2*)&a;
    #pragma unroll
    for (int i = 0; i < 2; i++) {
        float2 t = __half22float2(ah[i]);
        f[2 * i] = t.x; f[2 * i + 1] = t.y;
    }
}
template <int EPL>
__device__ __forceinline__ void loadv(int s, int lane, float* f) {
    if (EPL == 8) unpack8h(((const uint4*)g_vh)[(size_t)s * 32 + lane], f);
    else          unpack4h(((const uint2*)g_vh)[(size_t)s * 32 + lane], f);
}

template <int F>
__global__ __launch_bounds__(256) void attn_kernel(const float* __restrict__ bias) {
    __shared__ float ssum[F], ssq[F];
    int tid = threadIdx.x;
    int n = (blockIdx.x * blockDim.x + tid) >> 5;
    int lane = tid & 31;
    if (tid < F) { ssum[tid] = 0.f; ssq[tid] = 0.f; }
    __syncthreads();

    constexpr int EPL = F / 32;
    float hv[EPL];

    if (n < Nn) {
        int deg = g_deg[n];
        int base = g_inc[n] + g_boff[n >> 10] - deg;

        const uint4* qh = (const uint4*)g_qh;
        const uint4* kh = (const uint4*)g_kh;
        float acc[EPL];
        #pragma unroll
        for (int i = 0; i < EPL; i++) acc[i] = 0.f;
        float ssm = 0.f;

        if (deg > 0) {
            uint4 qreg = qh[(size_t)n * 32 + lane];
            float mx = -INFINITY;
            int j = 0;
            for (; j + 8 <= deg; j += 8) {
                int s[8]; float p[8];
                #pragma unroll
                for (int u = 0; u < 8; u++) s[u] = g_csr_src[base + j + u];
                #pragma unroll
                for (int u = 0; u < 8; u++) p[u] = dot8h(qreg, kh[(size_t)s[u] * 32 + lane]);
                #pragma unroll
                for (int off = 16; off; off >>= 1)
                    #pragma unroll
                    for (int u = 0; u < 8; u++)
                        p[u] += __shfl_xor_sync(0xffffffffu, p[u], off);
                float mnew = mx;
                #pragma unroll
                for (int u = 0; u < 8; u++) { p[u] *= 0.0625f; mnew = fmaxf(mnew, p[u]); }
                float corr = expf(mx - mnew);
                float e[8]; float esum = 0.f;
                #pragma unroll
                for (int u = 0; u < 8; u++) { e[u] = expf(p[u] - mnew); esum += e[u]; }
                ssm = ssm * corr + esum;
                float v0[EPL], v1[EPL], v2[EPL], v3[EPL];
                loadv<EPL>(s[0], lane, v0); loadv<EPL>(s[1], lane, v1);
                loadv<EPL>(s[2], lane, v2); loadv<EPL>(s[3], lane, v3);
                #pragma unroll
                for (int i = 0; i < EPL; i++)
                    acc[i] = acc[i] * corr + e[0] * v0[i] + e[1] * v1[i] + e[2] * v2[i] + e[3] * v3[i];
                loadv<EPL>(s[4], lane, v0); loadv<EPL>(s[5], lane, v1);
                loadv<EPL>(s[6], lane, v2); loadv<EPL>(s[7], lane, v3);
                #pragma unroll
                for (int i = 0; i < EPL; i++)
                    acc[i] += e[4] * v0[i] + e[5] * v1[i] + e[6] * v2[i] + e[7] * v3[i];
                mx = mnew;
            }
            for (; j + 4 <= deg; j += 4) {
                int s[4]; float p[4];
                #pragma unroll
                for (int u = 0; u < 4; u++) s[u] = g_csr_src[base + j + u];
                #pragma unroll
                for (int u = 0; u < 4; u++) p[u] = dot8h(qreg, kh[(size_t)s[u] * 32 + lane]);
                #pragma unroll
                for (int off = 16; off; off >>= 1)
                    #pragma unroll
                    for (int u = 0; u < 4; u++)
                        p[u] += __shfl_xor_sync(0xffffffffu, p[u], off);
                float mnew = mx;
                #pragma unroll
                for (int u = 0; u < 4; u++) { p[u] *= 0.0625f; mnew = fmaxf(mnew, p[u]); }
                float corr = expf(mx - mnew);
                float e[4]; float esum = 0.f;
                #pragma unroll
                for (int u = 0; u < 4; u++) { e[u] = expf(p[u] - mnew); esum += e[u]; }
                ssm = ssm * corr + esum;
                float v0[EPL], v1[EPL], v2[EPL], v3[EPL];
                loadv<EPL>(s[0], lane, v0); loadv<EPL>(s[1], lane, v1);
                loadv<EPL>(s[2], lane, v2); loadv<EPL>(s[3], lane, v3);
                #pragma unroll
                for (int i = 0; i < EPL; i++)
                    acc[i] = acc[i] * corr + e[0] * v0[i] + e[1] * v1[i] + e[2] * v2[i] + e[3] * v3[i];
                mx = mnew;
            }
            for (; j < deg; j++) {
                int s0 = g_csr_src[base + j];
                float p0 = dot8h(qreg, kh[(size_t)s0 * 32 + lane]);
                #pragma unroll
                for (int off = 16; off; off >>= 1)
                    p0 += __shfl_xor_sync(0xffffffffu, p0, off);
                p0 *= 0.0625f;
                float v0[EPL];
                loadv<EPL>(s0, lane, v0);
                float mnew = fmaxf(mx, p0);
                float corr = expf(mx - mnew);
                float e0 = expf(p0 - mnew);
                ssm = ssm * corr + e0;
                #pragma unroll
                for (int i = 0; i < EPL; i++)
                    acc[i] = acc[i] * corr + e0 * v0[i];
                mx = mnew;
            }
        }

        float inv = (deg > 0) ? 1.f / fmaxf(ssm, 1e-16f) : 0.f;
        float rv[EPL];
        if (EPL == 8) unpack8h(((const uint4*)g_rh)[(size_t)n * 32 + lane], rv);
        else          unpack4h(((const uint2*)g_rh)[(size_t)n * 32 + lane], rv);
        const float4* b4 = (const float4*)bias;
        int bo = lane * (EPL / 4);
        #pragma unroll
        for (int t = 0; t < EPL / 4; t++) {
            float4 bb = b4[bo + t];
            hv[4 * t + 0] = acc[4 * t + 0] * inv + rv[4 * t + 0] + bb.x;
            hv[4 * t + 1] = acc[4 * t + 1] * inv + rv[4 * t + 1] + bb.y;
            hv[4 * t + 2] = acc[4 * t + 2] * inv + rv[4 * t + 2] + bb.z;
            hv[4 * t + 3] = acc[4 * t + 3] * inv + rv[4 * t + 3] + bb.w;
        }
        if (EPL == 8) {
            uint4 pk;
            __half2* ph = (__half2*)&pk;
            #pragma unroll
            for (int i = 0; i < 4; i++) ph[i] = __floats2half2_rn(hv[2 * i], hv[2 * i + 1]);
            ((uint4*)g_hh)[(size_t)n * 32 + lane] = pk;
        } else {
            uint2 pk;
            __half2* ph = (__half2*)&pk;
            #pragma unroll
            for (int i = 0; i < 2; i++) ph[i] = __floats2half2_rn(hv[2 * i], hv[2 * i + 1]);
            ((uint2*)g_hh)[(size_t)n * 32 + lane] = pk;
        }
        #pragma unroll
        for (int i = 0; i < EPL; i++) {
            int f = lane * EPL + i;
            atomicAdd(&ssum[f], hv[i]);
            atomicAdd(&ssq[f], hv[i] * hv[i]);
        }
    }
    __syncthreads();
    if (tid < F) {
        atomicAdd(&g_sumf[tid], ssum[tid]);
        atomicAdd(&g_sumsqf[tid], ssq[tid]);
    }
}

// ---------------- batch norm finalize / apply ----------------
__global__ void bn_finalize_kernel(int F) {
    int f = threadIdx.x;
    if (f < F) {
        double mu = (double)g_sumf[f] / (double)Nn;
        double var = (double)g_sumsqf[f] / (double)Nn - mu * mu;
        if (var < 0.0) var = 0.0;
        g_mean[f] = (float)mu;
        g_inv[f] = (float)(1.0 / sqrt(var + 1e-5));
    }
    g_sumf[f] = 0.f;
    g_sumsqf[f] = 0.f;
}
__global__ void bn_apply_relu_kernel(const float* __restrict__ gam,
                                     const float* __restrict__ bet,
                                     __half* __restrict__ x1h, int F) {
    int i = blockIdx.x * blockDim.x + threadIdx.x;
    if (i < Nn * F) {
        int f = i % F;
        float v = (__half2float(g_hh[i]) - g_mean[f]) * g_inv[f] * gam[f] + bet[f];
        x1h[i] = __float2half(v > 0.f ? v : 0.f);
    }
}
__global__ void final_out_kernel(const float* __restrict__ gam,
                                 const float* __restrict__ bet,
                                 const float* __restrict__ x0,
                                 float* __restrict__ out) {
    int i = blockIdx.x * blockDim.x + threadIdx.x;
    if (i < Nn * IOd) {
        int f = i % IOd;
        float v = (__half2float(g_hh[i]) - g_mean[f]) * g_inv[f] * gam[f] + bet[f] + x0[i];
        out[i] = v > 0.f ? v : 0.f;
    }
}

// ---------------- launch sequence ----------------
extern "C" void kernel_launch(void* const* d_in, const int* in_sizes, int n_in,
                              void* d_out, int out_size) {
    const float* x0  = (const float*)d_in[0];
    const void*  edg = d_in[1];
    const float* b1  = (const float*)d_in[6];
    const float* g1  = (const float*)d_in[7];
    const float* be1 = (const float*)d_in[8];
    const float* b2  = (const float*)d_in[13];
    const float* g2  = (const float*)d_in[14];
    const float* be2 = (const float*)d_in[15];
    float* out = (float*)d_out;

    W8 ws;
    ws.w[0] = (const float*)d_in[2];
    ws.w[1] = (const float*)d_in[3];
    ws.w[2] = (const float*)d_in[4];
    ws.w[3] = (const float*)d_in[5];
    ws.w[4] = (const float*)d_in[9];
    ws.w[5] = (const float*)d_in[10];
    ws.w[6] = (const float*)d_in[11];
    ws.w[7] = (const float*)d_in[12];

    __half *pqh, *pkh, *pvh, *prh, *px0h, *px1h, *pwth;
    cudaGetSymbolAddress((void**)&pqh,  g_qh);
    cudaGetSymbolAddress((void**)&pkh,  g_kh);
    cudaGetSymbolAddress((void**)&pvh,  g_vh);
    cudaGetSymbolAddress((void**)&prh,  g_rh);
    cudaGetSymbolAddress((void**)&px0h, g_x0h);
    cudaGetSymbolAddress((void**)&px1h, g_x1h);
    cudaGetSymbolAddress((void**)&pwth, g_wth);

    const int SMEM_GEMM = (2 * 128 + 2 * 256) * SROWH * 2;   // 110592 bytes
    cudaFuncSetAttribute((const void*)fused_gemm_kernel<1>, cudaFuncAttributeMaxDynamicSharedMemorySize, SMEM_GEMM);
    cudaFuncSetAttribute((const void*)fused_gemm_kernel<2>, cudaFuncAttributeMaxDynamicSharedMemorySize, SMEM_GEMM);

    const int EDGE_BLOCKS = (Ee + 255) / 256;
    const int NODE_BLOCKS = (Nn + 255) / 256;
    const int NH_BLOCKS = (Nn * HIDd + 255) / 256;
    const int NI_BLOCKS = (Nn * IOd + 255) / 256;
    const int ATTN_BLOCKS = (Nn * 32 + 255) / 256;
    const int MB = (Nn + 127) / 128;
    const int PREP_BLOCKS = (PREP_TOTAL + 255) / 256;

    // order keeps fused_gemm<1> at launch index 3 (ncu profiles index 3)
    detect_zero_kernel<<<NODE_BLOCKS, 256>>>((const int*)edg);        // 0
    convert_count_kernel<<<EDGE_BLOCKS, 256>>>(edg);                  // 1
    prep_kernel<<<PREP_BLOCKS, 256>>>(ws, x0, pwth, px0h);            // 2
    fused_gemm_kernel<1><<<dim3(MB, 4), 512, SMEM_GEMM>>>(px0h, pwth + WT_L1, pqh, pkh, pvh, prh, Nn); // 3
    scan1_kernel<<<NB_SCAN, 1024>>>();                                // 4
    scan2_kernel<<<1, 64>>>();                                        // 5
    csr_scatter_kernel<<<EDGE_BLOCKS, 256>>>();                       // 6

    // ---- layer 1 ----
    attn_kernel<256><<<ATTN_BLOCKS, 256>>>(b1);
    bn_finalize_kernel<<<1, 256>>>(HIDd);
    bn_apply_relu_kernel<<<NH_BLOCKS, 256>>>(g1, be1, px1h, HIDd);

    // ---- layer 2 ----
    fused_gemm_kernel<2><<<dim3(MB, 3), 512, SMEM_GEMM>>>(px1h, pwth + WT_L2, pqh, pkh, pvh, prh, Nn);
    attn_kernel<128><<<ATTN_BLOCKS, 256>>>(b2);
    bn_finalize_kernel<<<1, 256>>>(IOd);
    final_out_kernel<<<NI_BLOCKS, 256>>>(g2, be2, x0, out);
}

// round 16
// speedup vs baseline: 1.0937x; 1.0937x over previous
#include <cuda_runtime.h>
#include <cuda_fp16.h>
#include <math.h>
#include <stdint.h>

// Problem constants (fixed by the reference)
#define Nn   50000
#define Ee   800000
#define IOd  128
#define HIDd 256
#define KQd  256

// ---------------- device scratch (no allocations allowed) ----------------
__device__ __half g_qh[Nn * KQd];
__device__ __half g_kh[Nn * KQd];
__device__ __half g_vh[Nn * HIDd];
__device__ __half g_rh[Nn * HIDd];
__device__ __half g_hh[Nn * HIDd];
__device__ __half g_x0h[Nn * IOd];
__device__ __half g_x1h[Nn * HIDd];
__device__ __half g_wth[327680];    // transposed fp16 weights
__device__ int   g_src[Ee];
__device__ int   g_dst[Ee];
__device__ int   g_csr_src[Ee];
__device__ int   g_deg[Nn];
__device__ int   g_inc[Nn];         // block-local inclusive scan of deg
__device__ int   g_fill[Nn];
#define NB_SCAN 49
__device__ int   g_bsum[NB_SCAN];
__device__ int   g_boff[NB_SCAN];   // exclusive block offsets
__device__ float g_sumf[HIDd];      // zero at call entry; finalize re-zeros
__device__ float g_sumsqf[HIDd];
__device__ float g_mean[HIDd];
__device__ float g_inv[HIDd];
__device__ int   g_flag64[1];
__device__ int   g_ticket[2];       // persistent-attn work counters (zeroed per call)

#define WT_L1 0         // [1024 x 128]: Q1,K1,V1,R1
#define WT_L2 131072    // [768 x 256]:  Q2,K2,V2,R2

// ---------------- helpers ----------------
__device__ __forceinline__ uint32_t smem_u32(const void* p) {
    uint32_t a;
    asm("{ .reg .u64 t; cvta.to.shared.u64 t, %1; cvt.u32.u64 %0, t; }" : "=r"(a) : "l"(p));
    return a;
}
__device__ __forceinline__ void cp_async16(uint32_t sm, const void* g) {
    asm volatile("cp.async.cg.shared.global [%0], [%1], 16;" :: "r"(sm), "l"(g));
}
__device__ __forceinline__ void cp_commit() { asm volatile("cp.async.commit_group;"); }
__device__ __forceinline__ void cp_wait1() { asm volatile("cp.async.wait_group 1;"); }
__device__ __forceinline__ void cp_wait0() { asm volatile("cp.async.wait_group 0;"); }
__device__ __forceinline__ void ldsm_x4(uint32_t& r0, uint32_t& r1, uint32_t& r2, uint32_t& r3,
                                        uint32_t addr) {
    asm volatile("ldmatrix.sync.aligned.m8n8.x4.shared.b16 {%0,%1,%2,%3}, [%4];"
                 : "=r"(r0), "=r"(r1), "=r"(r2), "=r"(r3) : "r"(addr));
}

// ---------------- prep: weight transpose->fp16 + x0->fp16 ----------------
struct W8 { const float* w[8]; };
#define PREP_W 327680
#define PREP_TOTAL (PREP_W + Nn * IOd)
__global__ void prep_kernel(W8 ws, const float* __restrict__ x0,
                            __half* __restrict__ Wt, __half* __restrict__ x0h) {
    int i = blockIdx.x * 256 + threadIdx.x;
    if (i >= PREP_TOTAL) return;
    if (i < PREP_W) {
        int seg, base, K, N, dst;
        if (i < 131072)      { seg = i >> 15;       base = seg << 15;          K = 128; N = 256; dst = seg * 32768; }
        else if (i < 262144) { seg = 4 + ((i - 131072) >> 16); base = 131072 + ((seg - 4) << 16); K = 256; N = 256; dst = 131072 + (seg - 4) * 65536; }
        else                 { seg = 6 + ((i - 262144) >> 15); base = 262144 + ((seg - 6) << 15); K = 256; N = 128; dst = 262144 + (seg - 6) * 32768; }
        int il = i - base;
        int k = il / N, n = il % N;
        Wt[dst + n * K + k] = __float2half(ws.w[seg][il]);
    } else {
        int j = i - PREP_W;
        x0h[j] = __float2half(x0[j]);
    }
}

// ---------------- fused HMMA fp16 GEMM: CTA 128x128, warp 64x32, ldmatrix ---
#define SROWH 72

template <int LAYER>
__global__ __launch_bounds__(256) void fused_gemm_kernel(
    const __half* __restrict__ A, const __half* __restrict__ BtAll,
    __half* __restrict__ Oq, __half* __restrict__ Ok,
    __half* __restrict__ Ov, __half* __restrict__ Orr, int M)
{
    constexpr int K = (LAYER == 1) ? 128 : 256;
    extern __shared__ __half smem[];
    __half* As = smem;                      // 2 x 128 x SROWH halves
    __half* Bs = smem + 2 * 128 * SROWH;

    const int tid = threadIdx.x;
    const int wid = tid >> 5;
    const int lane = tid & 31;
    const int gID = lane >> 2;
    const int tig = lane & 3;
    const int wm = (wid & 1) * 64;
    const int wn = (wid >> 1) * 32;
    const int m0 = blockIdx.x * 128;
    const int y = blockIdx.y;
    const int nb0 = y * 128;

    const int a_row_off = (lane & 15);
    const int a_col_off = (lane >> 4) << 3;
    const int b_row_off = (lane & 7) + ((lane >> 4) << 3);
    const int b_col_off = (lane & 8);

    float c[4][4][4] = {};
    constexpr int NC = K / 64;

    auto stage = [&](int cc, int buf) {
        const int k0 = cc * 64;
        __half* ab = As + buf * (128 * SROWH);
        __half* bb = Bs + buf * (128 * SROWH);
        #pragma unroll
        for (int i = 0; i < 4; i++) {
            int idx = tid + i * 256;
            int row = idx >> 3, g = idx & 7;
            int gr = m0 + row; if (gr >= M) gr = M - 1;
            cp_async16(smem_u32(ab + row * SROWH + g * 8), A + (size_t)gr * K + k0 + g * 8);
        }
        #pragma unroll
        for (int i = 0; i < 4; i++) {
            int idx = tid + i * 256;
            int row = idx >> 3, g = idx & 7;
            cp_async16(smem_u32(bb + row * SROWH + g * 8), BtAll + (size_t)(nb0 + row) * K + k0 + g * 8);
        }
        cp_commit();
    };

    stage(0, 0);
    for (int cc = 0; cc < NC; cc++) {
        const int buf = cc & 1;
        if (cc + 1 < NC) { stage(cc + 1, buf ^ 1); cp_wait1(); }
        else             { cp_wait0(); }
        __syncthreads();

        const __half* ab = As + buf * (128 * SROWH);
        const __half* bb = Bs + buf * (128 * SROWH);

        #pragma unroll
        for (int ks = 0; ks < 4; ks++) {
            const int kk = ks * 16;
            uint32_t af[4][4];
            #pragma unroll
            for (int mf = 0; mf < 4; mf++) {
                uint32_t addr = smem_u32(ab + (wm + mf * 16 + a_row_off) * SROWH + kk + a_col_off);
                ldsm_x4(af[mf][0], af[mf][1], af[mf][2], af[mf][3], addr);
            }
            uint32_t bf[4][2];
            #pragma unroll
            for (int np = 0; np < 2; np++) {
                uint32_t addr = smem_u32(bb + (wn + np * 16 + b_row_off) * SROWH + kk + b_col_off);
                ldsm_x4(bf[2 * np][0], bf[2 * np][1], bf[2 * np + 1][0], bf[2 * np + 1][1], addr);
            }
            #pragma unroll
            for (int mf = 0; mf < 4; mf++)
                #pragma unroll
                for (int nf = 0; nf < 4; nf++)
                    asm volatile(
                        "mma.sync.aligned.m16n8k16.row.col.f32.f16.f16.f32 "
                        "{%0,%1,%2,%3}, {%4,%5,%6,%7}, {%8,%9}, {%0,%1,%2,%3};"
                        : "+f"(c[mf][nf][0]), "+f"(c[mf][nf][1]),
                          "+f"(c[mf][nf][2]), "+f"(c[mf][nf][3])
                        : "r"(af[mf][0]), "r"(af[mf][1]), "r"(af[mf][2]), "r"(af[mf][3]),
                          "r"(bf[nf][0]), "r"(bf[nf][1]));
        }
        __syncthreads();
    }

    __half* hout; int Nout, cb;
    if (LAYER == 1) {
        int oi = y >> 1; cb = (y & 1) * 128; Nout = 256;
        hout = (oi == 0) ? Oq : (oi == 1) ? Ok : (oi == 2) ? Ov : Orr;
    } else {
        if (y < 4) { int oi = y >> 1; cb = (y & 1) * 128; Nout = 256; hout = (oi == 0) ? Oq : Ok; }
        else       { cb = 0; Nout = 128; hout = (y == 4) ? Ov : Orr; }
    }

    #pragma unroll
    for (int mf = 0; mf < 4; mf++) {
        int row = m0 + wm + mf * 16 + gID;
        #pragma unroll
        for (int nf = 0; nf < 4; nf++) {
            int col = cb + wn + nf * 8 + tig * 2;
            if (row < M)
                *(__half2*)(hout + (size_t)row * Nout + col) = __floats2half2_rn(c[mf][nf][0], c[mf][nf][1]);
            if (row + 8 < M)
                *(__half2*)(hout + (size_t)(row + 8) * Nout + col) = __floats2half2_rn(c[mf][nf][2], c[mf][nf][3]);
        }
    }
}

// ---------------- setup: zero + edge dtype detect ----------------
__global__ void detect_zero_kernel(const int* __restrict__ ew) {
    int i = blockIdx.x * blockDim.x + threadIdx.x;
    if (i < Nn) { g_deg[i] = 0; g_fill[i] = 0; }
    if (i < 2) g_ticket[i] = 0;
    if (blockIdx.x == 0) {
        __shared__ int nz;
        if (threadIdx.x == 0) nz = 0;
        __syncthreads();
        int stride = Ee / 256;
        int idx = 2 * (threadIdx.x * stride) + 1;
        if (ew[idx] != 0) atomicOr(&nz, 1);
        __syncthreads();
        if (threadIdx.x == 0) g_flag64[0] = nz ? 0 : 1;
    }
}

__global__ void convert_count_kernel(const void* __restrict__ edges) {
    int e = blockIdx.x * blockDim.x + threadIdx.x;
    if (e >= Ee) return;
    int s, d;
    if (g_flag64[0]) {
        const long long* p = (const long long*)edges;
        s = (int)p[e]; d = (int)p[Ee + e];
    } else {
        const int* p = (const int*)edges;
        s = p[e]; d = p[Ee + e];
    }
    g_src[e] = s; g_dst[e] = d;
    atomicAdd(&g_deg[d], 1);
}

// ---------------- CSR scan + scatter ----------------
__global__ void scan1_kernel() {
    __shared__ int sm[1024];
    int i = blockIdx.x * 1024 + threadIdx.x;
    int v = (i < Nn) ? g_deg[i] : 0;
    sm[threadIdx.x] = v;
    __syncthreads();
    for (int off = 1; off < 1024; off <<= 1) {
        int t = (threadIdx.x >= off) ? sm[threadIdx.x - off] : 0;
        __syncthreads();
        sm[threadIdx.x] += t;
        __syncthreads();
    }
    if (i < Nn) g_inc[i] = sm[threadIdx.x];
    if (threadIdx.x == 1023) g_bsum[blockIdx.x] = sm[1023];
}
__global__ void scan2_kernel() {
    __shared__ int sm[64];
    int t = threadIdx.x;
    sm[t] = (t < NB_SCAN) ? g_bsum[t] : 0;
    __syncthreads();
    #pragma unroll
    for (int off = 1; off < 64; off <<= 1) {
        int v = (t >= off) ? sm[t - off] : 0;
        __syncthreads();
        sm[t] += v;
        __syncthreads();
    }
    if (t < NB_SCAN) g_boff[t] = sm[t] - g_bsum[t];
}
__global__ void csr_scatter_kernel() {
    int e = blockIdx.x * blockDim.x + threadIdx.x;
    if (e >= Ee) return;
    int d = g_dst[e];
    int start = g_inc[d] + g_boff[d >> 10] - g_deg[d];
    int pos = start + atomicAdd(&g_fill[d], 1);
    g_csr_src[pos] = g_src[e];
}

// ---------------- attention: persistent warps, online softmax, fused BN ----
__device__ __forceinline__ float dot8h(uint4 a, uint4 b) {
    const __half2* ah = (const __half2*)&a;
    const __half2* bh = (const __half2*)&b;
    float p = 0.f;
    #pragma unroll
    for (int i = 0; i < 4; i++) {
        float2 fa = __half22float2(ah[i]);
        float2 fb = __half22float2(bh[i]);
        p += fa.x * fb.x + fa.y * fb.y;
    }
    return p;
}
__device__ __forceinline__ void unpack8h(uint4 a, float* f) {
    const __half2* ah = (const __half2*)&a;
    #pragma unroll
    for (int i = 0; i < 4; i++) {
        float2 t = __half22float2(ah[i]);
        f[2 * i] = t.x; f[2 * i + 1] = t.y;
    }
}
__device__ __forceinline__ void unpack4h(uint2 a, float* f) {
    const __half2* ah = (const __half2*)&a;
    #pragma unroll
    for (int i = 0; i < 2; i++) {
        float2 t = __half22float2(ah[i]);
        f[2 * i] = t.x; f[2 * i + 1] = t.y;
    }
}
template <int EPL>
__device__ __forceinline__ void loadv(int s, int lane, float* f) {
    if (EPL == 8) unpack8h(((const uint4*)g_vh)[(size_t)s * 32 + lane], f);
    else          unpack4h(((const uint2*)g_vh)[(size_t)s * 32 + lane], f);
}

template <int F, int TK>
__global__ __launch_bounds__(256) void attn_kernel(const float* __restrict__ bias) {
    __shared__ float ssum[F], ssq[F];
    int tid = threadIdx.x;
    int lane = tid & 31;
    if (tid < F) { ssum[tid] = 0.f; ssq[tid] = 0.f; }
    __syncthreads();

    constexpr int EPL = F / 32;
    const uint4* qh = (const uint4*)g_qh;
    const uint4* kh = (const uint4*)g_kh;

    for (;;) {
        int n;
        if (lane == 0) n = atomicAdd(&g_ticket[TK], 1);
        n = __shfl_sync(0xffffffffu, n, 0);
        if (n >= Nn) break;

        int deg = g_deg[n];
        int base = g_inc[n] + g_boff[n >> 10] - deg;

        float acc[EPL];
        #pragma unroll
        for (int i = 0; i < EPL; i++) acc[i] = 0.f;
        float ssm = 0.f;
        float hv[EPL];

        if (deg > 0) {
            uint4 qreg = qh[(size_t)n * 32 + lane];
            float mx = -INFINITY;
            int j = 0;
            for (; j + 8 <= deg; j += 8) {
                int s[8]; float p[8];
                #pragma unroll
                for (int u = 0; u < 8; u++) s[u] = g_csr_src[base + j + u];
                #pragma unroll
                for (int u = 0; u < 8; u++) p[u] = dot8h(qreg, kh[(size_t)s[u] * 32 + lane]);
                #pragma unroll
                for (int off = 16; off; off >>= 1)
                    #pragma unroll
                    for (int u = 0; u < 8; u++)
                        p[u] += __shfl_xor_sync(0xffffffffu, p[u], off);
                float mnew = mx;
                #pragma unroll
                for (int u = 0; u < 8; u++) { p[u] *= 0.0625f; mnew = fmaxf(mnew, p[u]); }
                float corr = expf(mx - mnew);
                float e[8]; float esum = 0.f;
                #pragma unroll
                for (int u = 0; u < 8; u++) { e[u] = expf(p[u] - mnew); esum += e[u]; }
                ssm = ssm * corr + esum;
                float v0[EPL], v1[EPL], v2[EPL], v3[EPL];
                loadv<EPL>(s[0], lane, v0); loadv<EPL>(s[1], lane, v1);
                loadv<EPL>(s[2], lane, v2); loadv<EPL>(s[3], lane, v3);
                #pragma unroll
                for (int i = 0; i < EPL; i++)
                    acc[i] = acc[i] * corr + e[0] * v0[i] + e[1] * v1[i] + e[2] * v2[i] + e[3] * v3[i];
                loadv<EPL>(s[4], lane, v0); loadv<EPL>(s[5], lane, v1);
                loadv<EPL>(s[6], lane, v2); loadv<EPL>(s[7], lane, v3);
                #pragma unroll
                for (int i = 0; i < EPL; i++)
                    acc[i] += e[4] * v0[i] + e[5] * v1[i] + e[6] * v2[i] + e[7] * v3[i];
                mx = mnew;
            }
            for (; j + 4 <= deg; j += 4) {
                int s[4]; float p[4];
                #pragma unroll
                for (int u = 0; u < 4; u++) s[u] = g_csr_src[base + j + u];
                #pragma unroll
                for (int u = 0; u < 4; u++) p[u] = dot8h(qreg, kh[(size_t)s[u] * 32 + lane]);
                #pragma unroll
                for (int off = 16; off; off >>= 1)
                    #pragma unroll
                    for (int u = 0; u < 4; u++)
                        p[u] += __shfl_xor_sync(0xffffffffu, p[u], off);
                float mnew = mx;
                #pragma unroll
                for (int u = 0; u < 4; u++) { p[u] *= 0.0625f; mnew = fmaxf(mnew, p[u]); }
                float corr = expf(mx - mnew);
                float e[4]; float esum = 0.f;
                #pragma unroll
                for (int u = 0; u < 4; u++) { e[u] = expf(p[u] - mnew); esum += e[u]; }
                ssm = ssm * corr + esum;
                float v0[EPL], v1[EPL], v2[EPL], v3[EPL];
                loadv<EPL>(s[0], lane, v0); loadv<EPL>(s[1], lane, v1);
                loadv<EPL>(s[2], lane, v2); loadv<EPL>(s[3], lane, v3);
                #pragma unroll
                for (int i = 0; i < EPL; i++)
                    acc[i] = acc[i] * corr + e[0] * v0[i] + e[1] * v1[i] + e[2] * v2[i] + e[3] * v3[i];
                mx = mnew;
            }
            for (; j < deg; j++) {
                int s0 = g_csr_src[base + j];
                float p0 = dot8h(qreg, kh[(size_t)s0 * 32 + lane]);
                #pragma unroll
                for (int off = 16; off; off >>= 1)
                    p0 += __shfl_xor_sync(0xffffffffu, p0, off);
                p0 *= 0.0625f;
                float v0[EPL];
                loadv<EPL>(s0, lane, v0);
                float mnew = fmaxf(mx, p0);
                float corr = expf(mx - mnew);
                float e0 = expf(p0 - mnew);
                ssm = ssm * corr + e0;
                #pragma unroll
                for (int i = 0; i < EPL; i++)
                    acc[i] = acc[i] * corr + e0 * v0[i];
                mx = mnew;
            }
        }

        float inv = (deg > 0) ? 1.f / fmaxf(ssm, 1e-16f) : 0.f;
        float rv[EPL];
        if (EPL == 8) unpack8h(((const uint4*)g_rh)[(size_t)n * 32 + lane], rv);
        else          unpack4h(((const uint2*)g_rh)[(size_t)n * 32 + lane], rv);
        const float4* b4 = (const float4*)bias;
        int bo = lane * (EPL / 4);
        #pragma unroll
        for (int t = 0; t < EPL / 4; t++) {
            float4 bb = b4[bo + t];
            hv[4 * t + 0] = acc[4 * t + 0] * inv + rv[4 * t + 0] + bb.x;
            hv[4 * t + 1] = acc[4 * t + 1] * inv + rv[4 * t + 1] + bb.y;
            hv[4 * t + 2] = acc[4 * t + 2] * inv + rv[4 * t + 2] + bb.z;
            hv[4 * t + 3] = acc[4 * t + 3] * inv + rv[4 * t + 3] + bb.w;
        }
        if (EPL == 8) {
            uint4 pk;
            __half2* ph = (__half2*)&pk;
            #pragma unroll
            for (int i = 0; i < 4; i++) ph[i] = __floats2half2_rn(hv[2 * i], hv[2 * i + 1]);
            ((uint4*)g_hh)[(size_t)n * 32 + lane] = pk;
        } else {
            uint2 pk;
            __half2* ph = (__half2*)&pk;
            #pragma unroll
            for (int i = 0; i < 2; i++) ph[i] = __floats2half2_rn(hv[2 * i], hv[2 * i + 1]);
            ((uint2*)g_hh)[(size_t)n * 32 + lane] = pk;
        }
        #pragma unroll
        for (int i = 0; i < EPL; i++) {
            int f = lane * EPL + i;
            atomicAdd(&ssum[f], hv[i]);
            atomicAdd(&ssq[f], hv[i] * hv[i]);
        }
    }

    __syncthreads();
    if (tid < F) {
        atomicAdd(&g_sumf[tid], ssum[tid]);
        atomicAdd(&g_sumsqf[tid], ssq[tid]);
    }
}

// ---------------- batch norm finalize / apply ----------------
__global__ void bn_finalize_kernel(int F) {
    int f = threadIdx.x;
    if (f < F) {
        double mu = (double)g_sumf[f] / (double)Nn;
        double var = (double)g_sumsqf[f] / (double)Nn - mu * mu;
        if (var < 0.0) var = 0.0;
        g_mean[f] = (float)mu;
        g_inv[f] = (float)(1.0 / sqrt(var + 1e-5));
    }
    g_sumf[f] = 0.f;
    g_sumsqf[f] = 0.f;
}
__global__ void bn_apply_relu_kernel(const float* __restrict__ gam,
                                     const float* __restrict__ bet,
                                     __half* __restrict__ x1h, int F) {
    int i = blockIdx.x * blockDim.x + threadIdx.x;
    if (i < Nn * F) {
        int f = i % F;
        float v = (__half2float(g_hh[i]) - g_mean[f]) * g_inv[f] * gam[f] + bet[f];
        x1h[i] = __float2half(v > 0.f ? v : 0.f);
    }
}
__global__ void final_out_kernel(const float* __restrict__ gam,
                                 const float* __restrict__ bet,
                                 const float* __restrict__ x0,
                                 float* __restrict__ out) {
    int i = blockIdx.x * blockDim.x + threadIdx.x;
    if (i < Nn * IOd) {
        int f = i % IOd;
        float v = (__half2float(g_hh[i]) - g_mean[f]) * g_inv[f] * gam[f] + bet[f] + x0[i];
        out[i] = v > 0.f ? v : 0.f;
    }
}

// ---------------- launch sequence ----------------
extern "C" void kernel_launch(void* const* d_in, const int* in_sizes, int n_in,
                              void* d_out, int out_size) {
    const float* x0  = (const float*)d_in[0];
    const void*  edg = d_in[1];
    const float* b1  = (const float*)d_in[6];
    const float* g1  = (const float*)d_in[7];
    const float* be1 = (const float*)d_in[8];
    const float* b2  = (const float*)d_in[13];
    const float* g2  = (const float*)d_in[14];
    const float* be2 = (const float*)d_in[15];
    float* out = (float*)d_out;

    W8 ws;
    ws.w[0] = (const float*)d_in[2];
    ws.w[1] = (const float*)d_in[3];
    ws.w[2] = (const float*)d_in[4];
    ws.w[3] = (const float*)d_in[5];
    ws.w[4] = (const float*)d_in[9];
    ws.w[5] = (const float*)d_in[10];
    ws.w[6] = (const float*)d_in[11];
    ws.w[7] = (const float*)d_in[12];

    __half *pqh, *pkh, *pvh, *prh, *px0h, *px1h, *pwth;
    cudaGetSymbolAddress((void**)&pqh,  g_qh);
    cudaGetSymbolAddress((void**)&pkh,  g_kh);
    cudaGetSymbolAddress((void**)&pvh,  g_vh);
    cudaGetSymbolAddress((void**)&prh,  g_rh);
    cudaGetSymbolAddress((void**)&px0h, g_x0h);
    cudaGetSymbolAddress((void**)&px1h, g_x1h);
    cudaGetSymbolAddress((void**)&pwth, g_wth);

    const int SMEM_GEMM = 4 * 128 * SROWH * 2;   // 73728 bytes
    cudaFuncSetAttribute((const void*)fused_gemm_kernel<1>, cudaFuncAttributeMaxDynamicSharedMemorySize, SMEM_GEMM);
    cudaFuncSetAttribute((const void*)fused_gemm_kernel<2>, cudaFuncAttributeMaxDynamicSharedMemorySize, SMEM_GEMM);

    const int EDGE_BLOCKS = (Ee + 255) / 256;
    const int NODE_BLOCKS = (Nn + 255) / 256;
    const int NH_BLOCKS = (Nn * HIDd + 255) / 256;
    const int NI_BLOCKS = (Nn * IOd + 255) / 256;
    const int ATTN_BLOCKS = 592;     // ~4 blocks/SM, persistent ticket dispatch
    const int MB = (Nn + 127) / 128;
    const int PREP_BLOCKS = (PREP_TOTAL + 255) / 256;

    // order keeps fused_gemm<1> at launch index 3 (ncu profiles index 3)
    detect_zero_kernel<<<NODE_BLOCKS, 256>>>((const int*)edg);        // 0
    convert_count_kernel<<<EDGE_BLOCKS, 256>>>(edg);                  // 1
    prep_kernel<<<PREP_BLOCKS, 256>>>(ws, x0, pwth, px0h);            // 2
    fused_gemm_kernel<1><<<dim3(MB, 8), 256, SMEM_GEMM>>>(px0h, pwth + WT_L1, pqh, pkh, pvh, prh, Nn); // 3
    scan1_kernel<<<NB_SCAN, 1024>>>();                                // 4
    scan2_kernel<<<1, 64>>>();                                        // 5
    csr_scatter_kernel<<<EDGE_BLOCKS, 256>>>();                       // 6

    // ---- layer 1 ----
    attn_kernel<256, 0><<<ATTN_BLOCKS, 256>>>(b1);
    bn_finalize_kernel<<<1, 256>>>(HIDd);
    bn_apply_relu_kernel<<<NH_BLOCKS, 256>>>(g1, be1, px1h, HIDd);

    // ---- layer 2 ----
    fused_gemm_kernel<2><<<dim3(MB, 6), 256, SMEM_GEMM>>>(px1h, pwth + WT_L2, pqh, pkh, pvh, prh, Nn);
    attn_kernel<128, 1><<<ATTN_BLOCKS, 256>>>(b2);
    bn_finalize_kernel<<<1, 256>>>(IOd);
    final_out_kernel<<<NI_BLOCKS, 256>>>(g2, be2, x0, out);
}

// round 17
// speedup vs baseline: 1.1112x; 1.0160x over previous
#include <cuda_runtime.h>
#include <cuda_fp16.h>
#include <math.h>
#include <stdint.h>

// Problem constants (fixed by the reference)
#define Nn   50000
#define Ee   800000
#define IOd  128
#define HIDd 256
#define KQd  256

// ---------------- device scratch (no allocations allowed) ----------------
__device__ __half g_qh[Nn * KQd];
__device__ __half g_kh[Nn * KQd];
__device__ __half g_vh[Nn * HIDd];
__device__ __half g_rh[Nn * HIDd];
__device__ __half g_hh[Nn * HIDd];
__device__ __half g_x0h[Nn * IOd];
__device__ __half g_x1h[Nn * HIDd];
__device__ __half g_wth[327680];    // transposed fp16 weights
__device__ int   g_src[Ee];
__device__ int   g_dst[Ee];
__device__ int   g_csr_src[Ee];
__device__ int   g_deg[Nn];
__device__ int   g_inc[Nn];         // block-local inclusive scan of deg
__device__ int   g_fill[Nn];
#define NB_SCAN 49
__device__ int   g_bsum[NB_SCAN];
__device__ int   g_boff[NB_SCAN];   // exclusive block offsets
__device__ float g_sumf[HIDd];      // zero at call entry; finalize re-zeros
__device__ float g_sumsqf[HIDd];
__device__ float g_mean[HIDd];
__device__ float g_inv[HIDd];
__device__ int   g_flag64[1];
__device__ int   g_ticket[2];       // persistent-attn work counters (zeroed per call)

#define WT_L1 0         // [1024 x 128]: Q1,K1,V1,R1
#define WT_L2 131072    // [768 x 256]:  Q2,K2,V2,R2

// ---------------- helpers ----------------
__device__ __forceinline__ uint32_t smem_u32(const void* p) {
    uint32_t a;
    asm("{ .reg .u64 t; cvta.to.shared.u64 t, %1; cvt.u32.u64 %0, t; }" : "=r"(a) : "l"(p));
    return a;
}
__device__ __forceinline__ void cp_async16(uint32_t sm, const void* g) {
    asm volatile("cp.async.cg.shared.global [%0], [%1], 16;" :: "r"(sm), "l"(g));
}
__device__ __forceinline__ void cp_commit() { asm volatile("cp.async.commit_group;"); }
__device__ __forceinline__ void cp_wait1() { asm volatile("cp.async.wait_group 1;"); }
__device__ __forceinline__ void cp_wait0() { asm volatile("cp.async.wait_group 0;"); }
__device__ __forceinline__ void ldsm_x4(uint32_t& r0, uint32_t& r1, uint32_t& r2, uint32_t& r3,
                                        uint32_t addr) {
    asm volatile("ldmatrix.sync.aligned.m8n8.x4.shared.b16 {%0,%1,%2,%3}, [%4];"
                 : "=r"(r0), "=r"(r1), "=r"(r2), "=r"(r3) : "r"(addr));
}

// ---------------- prep: weight transpose->fp16 + x0->fp16 ----------------
struct W8 { const float* w[8]; };
#define PREP_W 327680
#define PREP_TOTAL (PREP_W + Nn * IOd)
__global__ void prep_kernel(W8 ws, const float* __restrict__ x0,
                            __half* __restrict__ Wt, __half* __restrict__ x0h) {
    int i = blockIdx.x * 256 + threadIdx.x;
    if (i >= PREP_TOTAL) return;
    if (i < PREP_W) {
        int seg, base, K, N, dst;
        if (i < 131072)      { seg = i >> 15;       base = seg << 15;          K = 128; N = 256; dst = seg * 32768; }
        else if (i < 262144) { seg = 4 + ((i - 131072) >> 16); base = 131072 + ((seg - 4) << 16); K = 256; N = 256; dst = 131072 + (seg - 4) * 65536; }
        else                 { seg = 6 + ((i - 262144) >> 15); base = 262144 + ((seg - 6) << 15); K = 256; N = 128; dst = 262144 + (seg - 6) * 32768; }
        int il = i - base;
        int k = il / N, n = il % N;
        Wt[dst + n * K + k] = __float2half(ws.w[seg][il]);
    } else {
        int j = i - PREP_W;
        x0h[j] = __float2half(x0[j]);
    }
}

// ---------------- fused HMMA fp16 GEMM: CTA 128x128, warp 64x32, ldmatrix ---
#define SROWH 72

template <int LAYER>
__global__ __launch_bounds__(256) void fused_gemm_kernel(
    const __half* __restrict__ A, const __half* __restrict__ BtAll,
    __half* __restrict__ Oq, __half* __restrict__ Ok,
    __half* __restrict__ Ov, __half* __restrict__ Orr, int M)
{
    constexpr int K = (LAYER == 1) ? 128 : 256;
    extern __shared__ __half smem[];
    __half* As = smem;                      // 2 x 128 x SROWH halves
    __half* Bs = smem + 2 * 128 * SROWH;

    const int tid = threadIdx.x;
    const int wid = tid >> 5;
    const int lane = tid & 31;
    const int gID = lane >> 2;
    const int tig = lane & 3;
    const int wm = (wid & 1) * 64;
    const int wn = (wid >> 1) * 32;
    const int m0 = blockIdx.x * 128;
    const int y = blockIdx.y;
    const int nb0 = y * 128;

    const int a_row_off = (lane & 15);
    const int a_col_off = (lane >> 4) << 3;
    const int b_row_off = (lane & 7) + ((lane >> 4) << 3);
    const int b_col_off = (lane & 8);

    float c[4][4][4] = {};
    constexpr int NC = K / 64;

    auto stage = [&](int cc, int buf) {
        const int k0 = cc * 64;
        __half* ab = As + buf * (128 * SROWH);
        __half* bb = Bs + buf * (128 * SROWH);
        #pragma unroll
        for (int i = 0; i < 4; i++) {
            int idx = tid + i * 256;
            int row = idx >> 3, g = idx & 7;
            int gr = m0 + row; if (gr >= M) gr = M - 1;
            cp_async16(smem_u32(ab + row * SROWH + g * 8), A + (size_t)gr * K + k0 + g * 8);
        }
        #pragma unroll
        for (int i = 0; i < 4; i++) {
            int idx = tid + i * 256;
            int row = idx >> 3, g = idx & 7;
            cp_async16(smem_u32(bb + row * SROWH + g * 8), BtAll + (size_t)(nb0 + row) * K + k0 + g * 8);
        }
        cp_commit();
    };

    stage(0, 0);
    for (int cc = 0; cc < NC; cc++) {
        const int buf = cc & 1;
        if (cc + 1 < NC) { stage(cc + 1, buf ^ 1); cp_wait1(); }
        else             { cp_wait0(); }
        __syncthreads();

        const __half* ab = As + buf * (128 * SROWH);
        const __half* bb = Bs + buf * (128 * SROWH);

        #pragma unroll
        for (int ks = 0; ks < 4; ks++) {
            const int kk = ks * 16;
            uint32_t af[4][4];
            #pragma unroll
            for (int mf = 0; mf < 4; mf++) {
                uint32_t addr = smem_u32(ab + (wm + mf * 16 + a_row_off) * SROWH + kk + a_col_off);
                ldsm_x4(af[mf][0], af[mf][1], af[mf][2], af[mf][3], addr);
            }
            uint32_t bf[4][2];
            #pragma unroll
            for (int np = 0; np < 2; np++) {
                uint32_t addr = smem_u32(bb + (wn + np * 16 + b_row_off) * SROWH + kk + b_col_off);
                ldsm_x4(bf[2 * np][0], bf[2 * np][1], bf[2 * np + 1][0], bf[2 * np + 1][1], addr);
            }
            #pragma unroll
            for (int mf = 0; mf < 4; mf++)
                #pragma unroll
                for (int nf = 0; nf < 4; nf++)
                    asm volatile(
                        "mma.sync.aligned.m16n8k16.row.col.f32.f16.f16.f32 "
                        "{%0,%1,%2,%3}, {%4,%5,%6,%7}, {%8,%9}, {%0,%1,%2,%3};"
                        : "+f"(c[mf][nf][0]), "+f"(c[mf][nf][1]),
                          "+f"(c[mf][nf][2]), "+f"(c[mf][nf][3])
                        : "r"(af[mf][0]), "r"(af[mf][1]), "r"(af[mf][2]), "r"(af[mf][3]),
                          "r"(bf[nf][0]), "r"(bf[nf][1]));
        }
        __syncthreads();
    }

    __half* hout; int Nout, cb;
    if (LAYER == 1) {
        int oi = y >> 1; cb = (y & 1) * 128; Nout = 256;
        hout = (oi == 0) ? Oq : (oi == 1) ? Ok : (oi == 2) ? Ov : Orr;
    } else {
        if (y < 4) { int oi = y >> 1; cb = (y & 1) * 128; Nout = 256; hout = (oi == 0) ? Oq : Ok; }
        else       { cb = 0; Nout = 128; hout = (y == 4) ? Ov : Orr; }
    }

    #pragma unroll
    for (int mf = 0; mf < 4; mf++) {
        int row = m0 + wm + mf * 16 + gID;
        #pragma unroll
        for (int nf = 0; nf < 4; nf++) {
            int col = cb + wn + nf * 8 + tig * 2;
            if (row < M)
                *(__half2*)(hout + (size_t)row * Nout + col) = __floats2half2_rn(c[mf][nf][0], c[mf][nf][1]);
            if (row + 8 < M)
                *(__half2*)(hout + (size_t)(row + 8) * Nout + col) = __floats2half2_rn(c[mf][nf][2], c[mf][nf][3]);
        }
    }
}

// ---------------- setup: zero + edge dtype detect ----------------
__global__ void detect_zero_kernel(const int* __restrict__ ew) {
    int i = blockIdx.x * blockDim.x + threadIdx.x;
    if (i < Nn) { g_deg[i] = 0; g_fill[i] = 0; }
    if (i < 2) g_ticket[i] = 0;
    if (blockIdx.x == 0) {
        __shared__ int nz;
        if (threadIdx.x == 0) nz = 0;
        __syncthreads();
        int stride = Ee / 256;
        int idx = 2 * (threadIdx.x * stride) + 1;
        if (ew[idx] != 0) atomicOr(&nz, 1);
        __syncthreads();
        if (threadIdx.x == 0) g_flag64[0] = nz ? 0 : 1;
    }
}

__global__ void convert_count_kernel(const void* __restrict__ edges) {
    int e = blockIdx.x * blockDim.x + threadIdx.x;
    if (e >= Ee) return;
    int s, d;
    if (g_flag64[0]) {
        const long long* p = (const long long*)edges;
        s = (int)p[e]; d = (int)p[Ee + e];
    } else {
        const int* p = (const int*)edges;
        s = p[e]; d = p[Ee + e];
    }
    g_src[e] = s; g_dst[e] = d;
    atomicAdd(&g_deg[d], 1);
}

// ---------------- CSR scan + scatter ----------------
__global__ void scan1_kernel() {
    __shared__ int sm[1024];
    int i = blockIdx.x * 1024 + threadIdx.x;
    int v = (i < Nn) ? g_deg[i] : 0;
    sm[threadIdx.x] = v;
    __syncthreads();
    for (int off = 1; off < 1024; off <<= 1) {
        int t = (threadIdx.x >= off) ? sm[threadIdx.x - off] : 0;
        __syncthreads();
        sm[threadIdx.x] += t;
        __syncthreads();
    }
    if (i < Nn) g_inc[i] = sm[threadIdx.x];
    if (threadIdx.x == 1023) g_bsum[blockIdx.x] = sm[1023];
}
__global__ void scan2_kernel() {
    __shared__ int sm[64];
    int t = threadIdx.x;
    sm[t] = (t < NB_SCAN) ? g_bsum[t] : 0;
    __syncthreads();
    #pragma unroll
    for (int off = 1; off < 64; off <<= 1) {
        int v = (t >= off) ? sm[t - off] : 0;
        __syncthreads();
        sm[t] += v;
        __syncthreads();
    }
    if (t < NB_SCAN) g_boff[t] = sm[t] - g_bsum[t];
}
__global__ void csr_scatter_kernel() {
    int e = blockIdx.x * blockDim.x + threadIdx.x;
    if (e >= Ee) return;
    int d = g_dst[e];
    int start = g_inc[d] + g_boff[d >> 10] - g_deg[d];
    int pos = start + atomicAdd(&g_fill[d], 1);
    g_csr_src[pos] = g_src[e];
}

// ---------------- attention: persistent warps (batch-2 tickets) ------------
__device__ __forceinline__ float dot8h(uint4 a, uint4 b) {
    const __half2* ah = (const __half2*)&a;
    const __half2* bh = (const __half2*)&b;
    float p = 0.f;
    #pragma unroll
    for (int i = 0; i < 4; i++) {
        float2 fa = __half22float2(ah[i]);
        float2 fb = __half22float2(bh[i]);
        p += fa.x * fb.x + fa.y * fb.y;
    }
    return p;
}
__device__ __forceinline__ void unpack8h(uint4 a, float* f) {
    const __half2* ah = (const __half2*)&a;
    #pragma unroll
    for (int i = 0; i < 4; i++) {
        float2 t = __half22float2(ah[i]);
        f[2 * i] = t.x; f[2 * i + 1] = t.y;
    }
}
__device__ __forceinline__ void unpack4h(uint2 a, float* f) {
    const __half2* ah = (const __half2*)&a;
    #pragma unroll
    for (int i = 0; i < 2; i++) {
        float2 t = __half22float2(ah[i]);
        f[2 * i] = t.x; f[2 * i + 1] = t.y;
    }
}
template <int EPL>
__device__ __forceinline__ void loadv(int s, int lane, float* f) {
    if (EPL == 8) unpack8h(((const uint4*)g_vh)[(size_t)s * 32 + lane], f);
    else          unpack4h(((const uint2*)g_vh)[(size_t)s * 32 + lane], f);
}

template <int F, int TK>
__global__ __launch_bounds__(256) void attn_kernel(const float* __restrict__ bias) {
    __shared__ float ssum[F], ssq[F];
    int tid = threadIdx.x;
    int lane = tid & 31;
    if (tid < F) { ssum[tid] = 0.f; ssq[tid] = 0.f; }
    __syncthreads();

    constexpr int EPL = F / 32;
    const uint4* qh = (const uint4*)g_qh;
    const uint4* kh = (const uint4*)g_kh;

    for (;;) {
        int n0;
        if (lane == 0) n0 = atomicAdd(&g_ticket[TK], 2);
        n0 = __shfl_sync(0xffffffffu, n0, 0);
        if (n0 >= Nn) break;

        #pragma unroll 1
        for (int bi = 0; bi < 2; bi++) {
            int n = n0 + bi;
            if (n >= Nn) break;

            int deg = g_deg[n];
            int base = g_inc[n] + g_boff[n >> 10] - deg;

            float acc[EPL];
            #pragma unroll
            for (int i = 0; i < EPL; i++) acc[i] = 0.f;
            float ssm = 0.f;
            float hv[EPL];

            if (deg > 0) {
                uint4 qreg = qh[(size_t)n * 32 + lane];
                float mx = -INFINITY;
                int j = 0;
                for (; j + 8 <= deg; j += 8) {
                    int s[8]; float p[8];
                    #pragma unroll
                    for (int u = 0; u < 8; u++) s[u] = g_csr_src[base + j + u];
                    #pragma unroll
                    for (int u = 0; u < 8; u++) p[u] = dot8h(qreg, kh[(size_t)s[u] * 32 + lane]);
                    #pragma unroll
                    for (int off = 16; off; off >>= 1)
                        #pragma unroll
                        for (int u = 0; u < 8; u++)
                            p[u] += __shfl_xor_sync(0xffffffffu, p[u], off);
                    float mnew = mx;
                    #pragma unroll
                    for (int u = 0; u < 8; u++) { p[u] *= 0.0625f; mnew = fmaxf(mnew, p[u]); }
                    float corr = expf(mx - mnew);
                    float e[8]; float esum = 0.f;
                    #pragma unroll
                    for (int u = 0; u < 8; u++) { e[u] = expf(p[u] - mnew); esum += e[u]; }
                    ssm = ssm * corr + esum;
                    float v0[EPL], v1[EPL], v2[EPL], v3[EPL];
                    loadv<EPL>(s[0], lane, v0); loadv<EPL>(s[1], lane, v1);
                    loadv<EPL>(s[2], lane, v2); loadv<EPL>(s[3], lane, v3);
                    #pragma unroll
                    for (int i = 0; i < EPL; i++)
                        acc[i] = acc[i] * corr + e[0] * v0[i] + e[1] * v1[i] + e[2] * v2[i] + e[3] * v3[i];
                    loadv<EPL>(s[4], lane, v0); loadv<EPL>(s[5], lane, v1);
                    loadv<EPL>(s[6], lane, v2); loadv<EPL>(s[7], lane, v3);
                    #pragma unroll
                    for (int i = 0; i < EPL; i++)
                        acc[i] += e[4] * v0[i] + e[5] * v1[i] + e[6] * v2[i] + e[7] * v3[i];
                    mx = mnew;
                }
                for (; j + 4 <= deg; j += 4) {
                    int s[4]; float p[4];
                    #pragma unroll
                    for (int u = 0; u < 4; u++) s[u] = g_csr_src[base + j + u];
                    #pragma unroll
                    for (int u = 0; u < 4; u++) p[u] = dot8h(qreg, kh[(size_t)s[u] * 32 + lane]);
                    #pragma unroll
                    for (int off = 16; off; off >>= 1)
                        #pragma unroll
                        for (int u = 0; u < 4; u++)
                            p[u] += __shfl_xor_sync(0xffffffffu, p[u], off);
                    float mnew = mx;
                    #pragma unroll
                    for (int u = 0; u < 4; u++) { p[u] *= 0.0625f; mnew = fmaxf(mnew, p[u]); }
                    float corr = expf(mx - mnew);
                    float e[4]; float esum = 0.f;
                    #pragma unroll
                    for (int u = 0; u < 4; u++) { e[u] = expf(p[u] - mnew); esum += e[u]; }
                    ssm = ssm * corr + esum;
                    float v0[EPL], v1[EPL], v2[EPL], v3[EPL];
                    loadv<EPL>(s[0], lane, v0); loadv<EPL>(s[1], lane, v1);
                    loadv<EPL>(s[2], lane, v2); loadv<EPL>(s[3], lane, v3);
                    #pragma unroll
                    for (int i = 0; i < EPL; i++)
                        acc[i] = acc[i] * corr + e[0] * v0[i] + e[1] * v1[i] + e[2] * v2[i] + e[3] * v3[i];
                    mx = mnew;
                }
                for (; j < deg; j++) {
                    int s0 = g_csr_src[base + j];
                    float p0 = dot8h(qreg, kh[(size_t)s0 * 32 + lane]);
                    #pragma unroll
                    for (int off = 16; off; off >>= 1)
                        p0 += __shfl_xor_sync(0xffffffffu, p0, off);
                    p0 *= 0.0625f;
                    float v0[EPL];
                    loadv<EPL>(s0, lane, v0);
                    float mnew = fmaxf(mx, p0);
                    float corr = expf(mx - mnew);
                    float e0 = expf(p0 - mnew);
                    ssm = ssm * corr + e0;
                    #pragma unroll
                    for (int i = 0; i < EPL; i++)
                        acc[i] = acc[i] * corr + e0 * v0[i];
                    mx = mnew;
                }
            }

            float inv = (deg > 0) ? 1.f / fmaxf(ssm, 1e-16f) : 0.f;
            float rv[EPL];
            if (EPL == 8) unpack8h(((const uint4*)g_rh)[(size_t)n * 32 + lane], rv);
            else          unpack4h(((const uint2*)g_rh)[(size_t)n * 32 + lane], rv);
            const float4* b4 = (const float4*)bias;
            int bo = lane * (EPL / 4);
            #pragma unroll
            for (int t = 0; t < EPL / 4; t++) {
                float4 bb = b4[bo + t];
                hv[4 * t + 0] = acc[4 * t + 0] * inv + rv[4 * t + 0] + bb.x;
                hv[4 * t + 1] = acc[4 * t + 1] * inv + rv[4 * t + 1] + bb.y;
                hv[4 * t + 2] = acc[4 * t + 2] * inv + rv[4 * t + 2] + bb.z;
                hv[4 * t + 3] = acc[4 * t + 3] * inv + rv[4 * t + 3] + bb.w;
            }
            if (EPL == 8) {
                uint4 pk;
                __half2* ph = (__half2*)&pk;
                #pragma unroll
                for (int i = 0; i < 4; i++) ph[i] = __floats2half2_rn(hv[2 * i], hv[2 * i + 1]);
                ((uint4*)g_hh)[(size_t)n * 32 + lane] = pk;
            } else {
                uint2 pk;
                __half2* ph = (__half2*)&pk;
                #pragma unroll
                for (int i = 0; i < 2; i++) ph[i] = __floats2half2_rn(hv[2 * i], hv[2 * i + 1]);
                ((uint2*)g_hh)[(size_t)n * 32 + lane] = pk;
            }
            #pragma unroll
            for (int i = 0; i < EPL; i++) {
                int f = lane * EPL + i;
                atomicAdd(&ssum[f], hv[i]);
                atomicAdd(&ssq[f], hv[i] * hv[i]);
            }
        }
    }

    __syncthreads();
    if (tid < F) {
        atomicAdd(&g_sumf[tid], ssum[tid]);
        atomicAdd(&g_sumsqf[tid], ssq[tid]);
    }
}

// ---------------- batch norm finalize / apply ----------------
__global__ void bn_finalize_kernel(int F) {
    int f = threadIdx.x;
    if (f < F) {
        double mu = (double)g_sumf[f] / (double)Nn;
        double var = (double)g_sumsqf[f] / (double)Nn - mu * mu;
        if (var < 0.0) var = 0.0;
        g_mean[f] = (float)mu;
        g_inv[f] = (float)(1.0 / sqrt(var + 1e-5));
    }
    g_sumf[f] = 0.f;
    g_sumsqf[f] = 0.f;
}
__global__ void bn_apply_relu_kernel(const float* __restrict__ gam,
                                     const float* __restrict__ bet,
                                     __half* __restrict__ x1h, int F) {
    int i = blockIdx.x * blockDim.x + threadIdx.x;
    if (i < Nn * F) {
        int f = i % F;
        float v = (__half2float(g_hh[i]) - g_mean[f]) * g_inv[f] * gam[f] + bet[f];
        x1h[i] = __float2half(v > 0.f ? v : 0.f);
    }
}
__global__ void final_out_kernel(const float* __restrict__ gam,
                                 const float* __restrict__ bet,
                                 const float* __restrict__ x0,
                                 float* __restrict__ out) {
    int i = blockIdx.x * blockDim.x + threadIdx.x;
    if (i < Nn * IOd) {
        int f = i % IOd;
        float v = (__half2float(g_hh[i]) - g_mean[f]) * g_inv[f] * gam[f] + bet[f] + x0[i];
        out[i] = v > 0.f ? v : 0.f;
    }
}

// ---------------- launch sequence ----------------
extern "C" void kernel_launch(void* const* d_in, const int* in_sizes, int n_in,
                              void* d_out, int out_size) {
    const float* x0  = (const float*)d_in[0];
    const void*  edg = d_in[1];
    const float* b1  = (const float*)d_in[6];
    const float* g1  = (const float*)d_in[7];
    const float* be1 = (const float*)d_in[8];
    const float* b2  = (const float*)d_in[13];
    const float* g2  = (const float*)d_in[14];
    const float* be2 = (const float*)d_in[15];
    float* out = (float*)d_out;

    W8 ws;
    ws.w[0] = (const float*)d_in[2];
    ws.w[1] = (const float*)d_in[3];
    ws.w[2] = (const float*)d_in[4];
    ws.w[3] = (const float*)d_in[5];
    ws.w[4] = (const float*)d_in[9];
    ws.w[5] = (const float*)d_in[10];
    ws.w[6] = (const float*)d_in[11];
    ws.w[7] = (const float*)d_in[12];

    __half *pqh, *pkh, *pvh, *prh, *px0h, *px1h, *pwth;
    cudaGetSymbolAddress((void**)&pqh,  g_qh);
    cudaGetSymbolAddress((void**)&pkh,  g_kh);
    cudaGetSymbolAddress((void**)&pvh,  g_vh);
    cudaGetSymbolAddress((void**)&prh,  g_rh);
    cudaGetSymbolAddress((void**)&px0h, g_x0h);
    cudaGetSymbolAddress((void**)&px1h, g_x1h);
    cudaGetSymbolAddress((void**)&pwth, g_wth);

    // one-time side-stream + fork/join events (capture-legal; no device mem)
    static cudaStream_t s2 = nullptr;
    static cudaEvent_t evFork = nullptr, evJoin = nullptr;
    if (!s2) {
        cudaStreamCreateWithFlags(&s2, cudaStreamNonBlocking);
        cudaEventCreateWithFlags(&evFork, cudaEventDisableTiming);
        cudaEventCreateWithFlags(&evJoin, cudaEventDisableTiming);
    }

    const int SMEM_GEMM = 4 * 128 * SROWH * 2;   // 73728 bytes
    cudaFuncSetAttribute((const void*)fused_gemm_kernel<1>, cudaFuncAttributeMaxDynamicSharedMemorySize, SMEM_GEMM);
    cudaFuncSetAttribute((const void*)fused_gemm_kernel<2>, cudaFuncAttributeMaxDynamicSharedMemorySize, SMEM_GEMM);

    const int EDGE_BLOCKS = (Ee + 255) / 256;
    const int NODE_BLOCKS = (Nn + 255) / 256;
    const int NH_BLOCKS = (Nn * HIDd + 255) / 256;
    const int NI_BLOCKS = (Nn * IOd + 255) / 256;
    const int ATTN_BLOCKS = 592;     // ~4 blocks/SM, persistent ticket dispatch
    const int MB = (Nn + 127) / 128;
    const int PREP_BLOCKS = (PREP_TOTAL + 255) / 256;

    // fork: prep + GEMM<1> on s2, CSR build on main stream, join before attn
    cudaEventRecord(evFork, 0);
    cudaStreamWaitEvent(s2, evFork, 0);
    prep_kernel<<<PREP_BLOCKS, 256, 0, s2>>>(ws, x0, pwth, px0h);
    fused_gemm_kernel<1><<<dim3(MB, 8), 256, SMEM_GEMM, s2>>>(px0h, pwth + WT_L1, pqh, pkh, pvh, prh, Nn);
    cudaEventRecord(evJoin, s2);

    detect_zero_kernel<<<NODE_BLOCKS, 256>>>((const int*)edg);
    convert_count_kernel<<<EDGE_BLOCKS, 256>>>(edg);
    scan1_kernel<<<NB_SCAN, 1024>>>();
    scan2_kernel<<<1, 64>>>();
    csr_scatter_kernel<<<EDGE_BLOCKS, 256>>>();

    cudaStreamWaitEvent(0, evJoin, 0);

    // ---- layer 1 ----
    attn_kernel<256, 0><<<ATTN_BLOCKS, 256>>>(b1);
    bn_finalize_kernel<<<1, 256>>>(HIDd);
    bn_apply_relu_kernel<<<NH_BLOCKS, 256>>>(g1, be1, px1h, HIDd);

    // ---- layer 2 ----
    fused_gemm_kernel<2><<<dim3(MB, 6), 256, SMEM_GEMM>>>(px1h, pwth + WT_L2, pqh, pkh, pvh, prh, Nn);
    attn_kernel<128, 1><<<ATTN_BLOCKS, 256>>>(b2);
    bn_finalize_kernel<<<1, 256>>>(IOd);
    final_out_kernel<<<NI_BLOCKS, 256>>>(g2, be2, x0, out);
}